// round 5
// baseline (speedup 1.0000x reference)
#include <cuda_runtime.h>
#include <cuda_bf16.h>
#include <math.h>

// Fixed problem constants (IGMC dataset)
#define NMAX 100000
#define EMAX 1600000
#define RR   5
#define DD   32
#define NBB  2
#define FF   4
#define CC   5
#define BMAX 512
#define FULLM 0xffffffffu

// ---------------- scratch (device globals; no allocation) ----------------
__device__ float g_h0[NMAX * DD];
__device__ float g_h1[NMAX * DD];
__device__ int   g_cntNR[NMAX * RR];
__device__ int   g_rowptr[NMAX + 1];
__device__ int   g_cursor[NMAX];
__device__ int   g_blocksums[256];
__device__ int   g_blockoff[256];
__device__ unsigned long long g_recs[EMAX];             // {w_f32 | (src<<3|rel)} dst-sorted
__device__ float g_W[96 * DD];                          // combined [root; basis0; basis1]
__device__ float g_concat[BMAX * 4 * DD];

__device__ __forceinline__ const float* hbuf_in(int sel, const float* ext) {
    return (sel == 1) ? g_h0 : ((sel == 2) ? g_h1 : ext);
}
__device__ __forceinline__ float* hbuf_out(int sel) {
    return (sel == 1) ? g_h0 : g_h1;
}

// ---------------- CSR build ----------------
__global__ void k_zero_cnt(int n) {
    int i = blockIdx.x * blockDim.x + threadIdx.x;
    if (i < n) g_cntNR[i] = 0;
}

__global__ void k_count(const int* __restrict__ ei, const int* __restrict__ et, int E) {
    int e = blockIdx.x * blockDim.x + threadIdx.x;
    if (e >= E) return;
    int d = ei[E + e];
    int t = et[e];
    atomicAdd(&g_cntNR[d * RR + t], 1);
}

__global__ void k_scanA(int N) {
    __shared__ int s[1024];
    int t = threadIdx.x;
    int i = blockIdx.x * 1024 + t;
    int v = 0;
    if (i < N) {
        int base = i * RR;
#pragma unroll
        for (int r = 0; r < RR; r++) v += g_cntNR[base + r];
    }
    s[t] = v;
    __syncthreads();
    for (int st = 1; st < 1024; st <<= 1) {
        int x = (t >= st) ? s[t - st] : 0;
        __syncthreads();
        s[t] += x;
        __syncthreads();
    }
    if (i < N) g_rowptr[i] = s[t];
    if (t == 1023) g_blocksums[blockIdx.x] = s[1023];
}

__global__ void k_scanB(int nblk) {
    __shared__ int s[256];
    int t = threadIdx.x;
    s[t] = (t < nblk) ? g_blocksums[t] : 0;
    __syncthreads();
    for (int st = 1; st < 256; st <<= 1) {
        int x = (t >= st) ? s[t - st] : 0;
        __syncthreads();
        s[t] += x;
        __syncthreads();
    }
    if (t < nblk) g_blockoff[t] = s[t] - g_blocksums[t];
}

__global__ void k_scanC(int N, int E) {
    int t = threadIdx.x;
    int i = blockIdx.x * 1024 + t;
    if (i < N) {
        int base = i * RR;
        int deg = 0;
#pragma unroll
        for (int r = 0; r < RR; r++) deg += g_cntNR[base + r];
        int excl = g_rowptr[i] - deg + g_blockoff[blockIdx.x];
        g_rowptr[i] = excl;
        g_cursor[i] = excl;
    }
    if (i == 0) g_rowptr[N] = E;
}

__global__ void k_fill(const int* __restrict__ ei, const int* __restrict__ et, int E) {
    int e = blockIdx.x * blockDim.x + threadIdx.x;
    if (e >= E) return;
    int s = ei[e];
    int d = ei[E + e];
    int t = et[e];
    int p = atomicAdd(&g_cursor[d], 1);
    int c = g_cntNR[d * RR + t];
    float w = 1.0f / (float)c;
    unsigned long long rec =
        (unsigned long long)(unsigned)((s << 3) | t) |
        ((unsigned long long)__float_as_uint(w) << 32);
    g_recs[p] = rec;
}

// ---------------- per-layer ----------------
// g_W[k][d], k in [0,3I): rows = [root(I); basis0(I); basis1(I)]
__global__ void k_buildW(const float* __restrict__ root, const float* __restrict__ basis, int I) {
    int idx = blockIdx.x * blockDim.x + threadIdx.x;
    int K = 3 * I;
    if (idx >= K * DD) return;
    int k = idx >> 5, d = idx & 31;
    float v;
    if (k < I) v = root[k * DD + d];
    else {
        int kk = k - I;
        int b = (kk >= I) ? 1 : 0;
        int i = kk - b * I;
        v = basis[(b * I + i) * DD + d];
    }
    g_W[idx] = v;
}

// Fused layer: per node n (one warp, lane = out dim d):
//   a_b[i]  = sum_{e into n} (w_e * comp[r_e, b]) * h[src_e][i]   (basis space, b=0,1)
//   out[n]  = tanh( bias + [h[n] | a_0 | a_1] @ W )
template <int I>
__global__ void __launch_bounds__(256, 2) k_layer(const float* __restrict__ hext, int inSel,
                                                  const float* __restrict__ comp,
                                                  const float* __restrict__ bias,
                                                  int outSel, int N) {
    constexpr int K = 3 * I;
    const float* __restrict__ h = hbuf_in(inSel, hext);
    float* __restrict__ out = hbuf_out(outSel);
    int lane = threadIdx.x & 31;

    // per-warp persistent state: W column for this lane + comp table in registers
    float w[K];
#pragma unroll
    for (int k = 0; k < K; k++) w[k] = g_W[k * DD + lane];
    float bv = bias[lane];
    float c0reg = (lane < RR) ? comp[lane * NBB + 0] : 0.f;
    float c1reg = (lane < RR) ? comp[lane * NBB + 1] : 0.f;

    int warpG = (blockIdx.x * blockDim.x + threadIdx.x) >> 5;
    int nwarps = (gridDim.x * blockDim.x) >> 5;

    for (int n = warpG; n < N; n += nwarps) {
        float a0 = 0.f, a1 = 0.f;
        int beg = g_rowptr[n];
        int end = g_rowptr[n + 1];
        for (int base = beg; base < end; base += 32) {
            int k = base + lane;
            unsigned long long rec = (k < end) ? g_recs[k] : 0ull;
            unsigned lo = (unsigned)rec;
            float wn = __uint_as_float((unsigned)(rec >> 32));
            int srcL = (int)(lo >> 3);
            int rel = (int)(lo & 7);
            // per-lane batch setup: fold comp into the weight once
            float wc0L = wn * __shfl_sync(FULLM, c0reg, rel);
            float wc1L = wn * __shfl_sync(FULLM, c1reg, rel);
            int cnt = min(32, end - base);
            for (int j = 0; j < cnt; j += 8) {
#pragma unroll
                for (int u = 0; u < 8; u++) {
                    int jj = j + u;
                    if (jj < cnt) {
                        int s = __shfl_sync(FULLM, srcL, jj);
                        float u0 = __shfl_sync(FULLM, wc0L, jj);
                        float u1 = __shfl_sync(FULLM, wc1L, jj);
                        float v;
                        if (I == DD) v = h[s * DD + lane];
                        else v = (lane < I) ? h[s * I + lane] : 0.f;
                        a0 += u0 * v;
                        a1 += u1 * v;
                    }
                }
            }
        }
        // fused transform
        float acc;
        if (I == DD) {
            float i0 = h[n * DD + lane];
            float p0 = bv, p1 = 0.f, p2 = 0.f;
#pragma unroll
            for (int k2 = 0; k2 < 32; k2++) p0 += __shfl_sync(FULLM, i0, k2) * w[k2];
#pragma unroll
            for (int k2 = 0; k2 < 32; k2++) p1 += __shfl_sync(FULLM, a0, k2) * w[32 + k2];
#pragma unroll
            for (int k2 = 0; k2 < 32; k2++) p2 += __shfl_sync(FULLM, a1, k2) * w[64 + k2];
            acc = p0 + p1 + p2;
        } else {
            float hv = (lane < I) ? h[n * I + lane] : 0.f;
            float a0b = __shfl_sync(FULLM, a0, lane & (I - 1));
            float a1b = __shfl_sync(FULLM, a1, lane & (I - 1));
            float iv = (lane < I) ? hv : ((lane < 2 * I) ? a0b : ((lane < 3 * I) ? a1b : 0.f));
            acc = bv;
#pragma unroll
            for (int k2 = 0; k2 < K; k2++) acc += __shfl_sync(FULLM, iv, k2) * w[k2];
        }
        out[n * DD + lane] = tanhf(acc);
    }
}

__global__ void k_gather(int hSel, const int* __restrict__ start, int layer) {
    const float* __restrict__ h = (hSel == 1) ? g_h0 : g_h1;
    int b = blockIdx.x;
    int lane = threadIdx.x;
    int node = start[b];
    g_concat[b * (4 * DD) + layer * DD + lane] = h[node * DD + lane];
}

__global__ void k_mlp(const float* __restrict__ w1, const float* __restrict__ b1,
                      const float* __restrict__ w2, const float* __restrict__ b2,
                      float* __restrict__ out) {
    __shared__ float cs[128];
    __shared__ float h1[128];
    __shared__ float lg[CC];
    int b = blockIdx.x;
    int t = threadIdx.x;
    cs[t] = g_concat[b * 128 + t];
    __syncthreads();
    float s = b1[t];
#pragma unroll 8
    for (int k = 0; k < 128; k++) s += cs[k] * w1[k * 128 + t];
    h1[t] = fmaxf(s, 0.f);
    __syncthreads();
    if (t < CC) {
        float s2 = b2[t];
#pragma unroll 8
        for (int k = 0; k < 128; k++) s2 += h1[k] * w2[k * CC + t];
        lg[t] = s2;
    }
    __syncthreads();
    if (t < CC) {
        float m = lg[0];
#pragma unroll
        for (int c = 1; c < CC; c++) m = fmaxf(m, lg[c]);
        float sum = 0.f;
#pragma unroll
        for (int c = 0; c < CC; c++) sum += expf(lg[c] - m);
        out[b * CC + t] = lg[t] - m - logf(sum);
    }
}

// ---------------- launch ----------------
extern "C" void kernel_launch(void* const* d_in, const int* in_sizes, int n_in,
                              void* d_out, int out_size) {
    const float* x      = (const float*)d_in[0];
    const int*   ei     = (const int*)d_in[1];
    const int*   et     = (const int*)d_in[2];
    const int*   start  = (const int*)d_in[3];
    const float* basis0 = (const float*)d_in[4];
    const float* comp0  = (const float*)d_in[5];
    const float* root0  = (const float*)d_in[6];
    const float* bias0  = (const float*)d_in[7];
    const float* basis  = (const float*)d_in[8];
    const float* comp   = (const float*)d_in[9];
    const float* root   = (const float*)d_in[10];
    const float* bias   = (const float*)d_in[11];
    const float* l1w    = (const float*)d_in[12];
    const float* l1b    = (const float*)d_in[13];
    const float* l2w    = (const float*)d_in[14];
    const float* l2b    = (const float*)d_in[15];
    float* out = (float*)d_out;

    int N = in_sizes[0] / FF;
    int E = in_sizes[2];
    int B = in_sizes[3];

    // ---- CSR build ----
    k_zero_cnt<<<(N * RR + 255) / 256, 256>>>(N * RR);
    k_count<<<(E + 255) / 256, 256>>>(ei, et, E);
    int nblk = (N + 1023) / 1024;
    k_scanA<<<nblk, 1024>>>(N);
    k_scanB<<<1, 256>>>(nblk);
    k_scanC<<<nblk, 1024>>>(N, E);
    k_fill<<<(E + 255) / 256, 256>>>(ei, et, E);

    const int layerGrid = 296;   // 2 blocks/SM x 148 SMs

    // ---- layer 0 (in = x, F=4) ----
    k_buildW<<<(3 * FF * DD + 255) / 256, 256>>>(root0, basis0, FF);
    k_layer<FF><<<layerGrid, 256>>>(x, 0, comp0, bias0, /*outSel=*/1, N);
    k_gather<<<B, 32>>>(1, start, 0);

    // ---- layers 1..3 ----
    int inSel = 1;
    for (int l = 0; l < 3; l++) {
        int outSel = (inSel == 1) ? 2 : 1;
        k_buildW<<<(3 * DD * DD + 255) / 256, 256>>>(
            root + (size_t)l * DD * DD, basis + (size_t)l * NBB * DD * DD, DD);
        k_layer<DD><<<layerGrid, 256>>>(nullptr, inSel, comp + (size_t)l * RR * NBB,
                                        bias + (size_t)l * DD, outSel, N);
        k_gather<<<B, 32>>>(outSel, start, l + 1);
        inSel = outSel;
    }

    // ---- readout MLP + log_softmax ----
    k_mlp<<<B, 128>>>(l1w, l1b, l2w, l2b, out);
}

// round 6
// speedup vs baseline: 1.8779x; 1.8779x over previous
#include <cuda_runtime.h>
#include <cuda_fp16.h>
#include <math.h>

// Fixed problem constants (IGMC dataset)
#define NMAX 100000
#define EMAX 1600000
#define RR   5
#define DD   32
#define NBB  2
#define FF   4
#define CC   5
#define BMAX 512
#define FULLM 0xffffffffu

// ---------------- scratch (device globals; no allocation) ----------------
__device__ __half g_h0[NMAX * DD];                      // 6.4 MB (fp16 node states)
__device__ __half g_h1[NMAX * DD];                      // 6.4 MB
__device__ float g_agg[NMAX * 2 * DD];                  // basis-space accumulators (fp32)
__device__ int   g_cntNR[NMAX * RR];
__device__ int   g_rowptr[NMAX + 1];
__device__ int   g_cursor[NMAX];
__device__ int   g_blocksums[256];
__device__ int   g_blockoff[256];
__device__ unsigned long long g_recs[EMAX];             // {w_f32 | (src<<3|rel)} dst-sorted
__device__ float g_W[96 * DD];                          // combined [root; basis0; basis1]
__device__ float g_concat[BMAX * 4 * DD];

// ---------------- CSR build ----------------
__global__ void k_zero_cnt(int n) {
    int i = blockIdx.x * blockDim.x + threadIdx.x;
    if (i < n) g_cntNR[i] = 0;
}

__global__ void k_count(const int* __restrict__ ei, const int* __restrict__ et, int E) {
    int e = blockIdx.x * blockDim.x + threadIdx.x;
    if (e >= E) return;
    int d = ei[E + e];
    int t = et[e];
    atomicAdd(&g_cntNR[d * RR + t], 1);
}

__global__ void k_scanA(int N) {
    __shared__ int s[1024];
    int t = threadIdx.x;
    int i = blockIdx.x * 1024 + t;
    int v = 0;
    if (i < N) {
        int base = i * RR;
#pragma unroll
        for (int r = 0; r < RR; r++) v += g_cntNR[base + r];
    }
    s[t] = v;
    __syncthreads();
    for (int st = 1; st < 1024; st <<= 1) {
        int x = (t >= st) ? s[t - st] : 0;
        __syncthreads();
        s[t] += x;
        __syncthreads();
    }
    if (i < N) g_rowptr[i] = s[t];
    if (t == 1023) g_blocksums[blockIdx.x] = s[1023];
}

__global__ void k_scanB(int nblk) {
    __shared__ int s[256];
    int t = threadIdx.x;
    s[t] = (t < nblk) ? g_blocksums[t] : 0;
    __syncthreads();
    for (int st = 1; st < 256; st <<= 1) {
        int x = (t >= st) ? s[t - st] : 0;
        __syncthreads();
        s[t] += x;
        __syncthreads();
    }
    if (t < nblk) g_blockoff[t] = s[t] - g_blocksums[t];
}

__global__ void k_scanC(int N, int E) {
    int t = threadIdx.x;
    int i = blockIdx.x * 1024 + t;
    if (i < N) {
        int base = i * RR;
        int deg = 0;
#pragma unroll
        for (int r = 0; r < RR; r++) deg += g_cntNR[base + r];
        int excl = g_rowptr[i] - deg + g_blockoff[blockIdx.x];
        g_rowptr[i] = excl;
        g_cursor[i] = excl;
    }
    if (i == 0) g_rowptr[N] = E;
}

__global__ void k_fill(const int* __restrict__ ei, const int* __restrict__ et, int E) {
    int e = blockIdx.x * blockDim.x + threadIdx.x;
    if (e >= E) return;
    int s = ei[e];
    int d = ei[E + e];
    int t = et[e];
    int p = atomicAdd(&g_cursor[d], 1);
    int c = g_cntNR[d * RR + t];
    float w = 1.0f / (float)c;
    unsigned long long rec =
        (unsigned long long)(unsigned)((s << 3) | t) |
        ((unsigned long long)__float_as_uint(w) << 32);
    g_recs[p] = rec;
}

// ---------------- per-layer ----------------
// g_W[k][d], k in [0,3I): rows = [root(I); basis0(I); basis1(I)]
__global__ void k_buildW(const float* __restrict__ root, const float* __restrict__ basis, int I) {
    int idx = blockIdx.x * blockDim.x + threadIdx.x;
    int K = 3 * I;
    if (idx >= K * DD) return;
    int k = idx >> 5, d = idx & 31;
    float v;
    if (k < I) v = root[k * DD + d];
    else {
        int kk = k - I;
        int b = (kk >= I) ? 1 : 0;
        int i = kk - b * I;
        v = basis[(b * I + i) * DD + d];
    }
    g_W[idx] = v;
}

// Edge aggregation in basis space (lean kernel, high occupancy):
//   accB_b[n][i] = sum_{e: dst=n} (w_e * comp[r_e,b]) * h[src_e][i]
// Layer 0 reads external fp32 x (I=FF); layers 1..3 read fp16 h (I=DD).
template <int I, typename T>
__global__ void k_edge(const T* __restrict__ h, const float* __restrict__ comp, int N) {
    int warp = threadIdx.x >> 5, lane = threadIdx.x & 31;
    int n = blockIdx.x * 8 + warp;
    if (n >= N) return;

    float c0reg = (lane < RR) ? comp[lane * NBB + 0] : 0.f;
    float c1reg = (lane < RR) ? comp[lane * NBB + 1] : 0.f;

    float a0 = 0.f, a1 = 0.f;
    int beg = g_rowptr[n];
    int end = g_rowptr[n + 1];
    for (int base = beg; base < end; base += 32) {
        int k = base + lane;
        unsigned long long rec = (k < end) ? g_recs[k] : 0ull;
        unsigned lo = (unsigned)rec;
        float wn = __uint_as_float((unsigned)(rec >> 32));
        int srcL = (int)(lo >> 3);
        int rel = (int)(lo & 7);
        // fold comp into the edge weight once per lane (batch setup)
        float wc0L = wn * __shfl_sync(FULLM, c0reg, rel);
        float wc1L = wn * __shfl_sync(FULLM, c1reg, rel);
        int cnt = min(32, end - base);
        for (int j = 0; j < cnt; j += 8) {
#pragma unroll
            for (int u = 0; u < 8; u++) {
                int jj = j + u;
                if (jj < cnt) {
                    int s = __shfl_sync(FULLM, srcL, jj);
                    float u0 = __shfl_sync(FULLM, wc0L, jj);
                    float u1 = __shfl_sync(FULLM, wc1L, jj);
                    float v;
                    if (I == DD) v = (float)h[s * DD + lane];
                    else v = (lane < I) ? (float)h[s * I + lane] : 0.f;
                    a0 += u0 * v;
                    a1 += u1 * v;
                }
            }
        }
    }
    if (I == DD) {
        g_agg[n * 64 + lane] = a0;
        g_agg[n * 64 + 32 + lane] = a1;
    } else if (lane < I) {
        g_agg[n * (2 * I) + lane] = a0;
        g_agg[n * (2 * I) + I + lane] = a1;
    }
}

// Fused transform: out[n][:] = tanh( bias + [h[n] | accB0 | accB1] @ g_W ), out in fp16
template <int I, typename T>
__global__ void __launch_bounds__(256) k_trans(const T* __restrict__ h,
                                               const float* __restrict__ bias,
                                               __half* __restrict__ out, int N) {
    constexpr int K = 3 * I;
    int lane = threadIdx.x & 31;
    float w[K];
#pragma unroll
    for (int k = 0; k < K; k++) w[k] = g_W[k * DD + lane];
    float bv = bias[lane];

    int warpG = (blockIdx.x * blockDim.x + threadIdx.x) >> 5;
    int nwarps = (gridDim.x * blockDim.x) >> 5;
    for (int n = warpG; n < N; n += nwarps) {
        float acc = bv;
        if (I == DD) {
            float i0 = (float)h[n * DD + lane];
            float i1 = g_agg[n * 64 + lane];
            float i2 = g_agg[n * 64 + 32 + lane];
#pragma unroll
            for (int k = 0; k < 32; k++) acc += __shfl_sync(FULLM, i0, k) * w[k];
#pragma unroll
            for (int k = 0; k < 32; k++) acc += __shfl_sync(FULLM, i1, k) * w[32 + k];
#pragma unroll
            for (int k = 0; k < 32; k++) acc += __shfl_sync(FULLM, i2, k) * w[64 + k];
        } else {
            float i0 = 0.f;
            if (lane < I) i0 = (float)h[n * I + lane];
            else if (lane < K) i0 = g_agg[n * (2 * I) + (lane - I)];
#pragma unroll
            for (int k = 0; k < K; k++) acc += __shfl_sync(FULLM, i0, k) * w[k];
        }
        out[n * DD + lane] = __float2half(tanhf(acc));
    }
}

__global__ void k_gather(const __half* __restrict__ h, const int* __restrict__ start, int layer) {
    int b = blockIdx.x;
    int lane = threadIdx.x;
    int node = start[b];
    g_concat[b * (4 * DD) + layer * DD + lane] = (float)h[node * DD + lane];
}

__global__ void k_mlp(const float* __restrict__ w1, const float* __restrict__ b1,
                      const float* __restrict__ w2, const float* __restrict__ b2,
                      float* __restrict__ out) {
    __shared__ float cs[128];
    __shared__ float h1[128];
    __shared__ float lg[CC];
    int b = blockIdx.x;
    int t = threadIdx.x;
    cs[t] = g_concat[b * 128 + t];
    __syncthreads();
    float s = b1[t];
#pragma unroll 8
    for (int k = 0; k < 128; k++) s += cs[k] * w1[k * 128 + t];
    h1[t] = fmaxf(s, 0.f);
    __syncthreads();
    if (t < CC) {
        float s2 = b2[t];
#pragma unroll 8
        for (int k = 0; k < 128; k++) s2 += h1[k] * w2[k * CC + t];
        lg[t] = s2;
    }
    __syncthreads();
    if (t < CC) {
        float m = lg[0];
#pragma unroll
        for (int c = 1; c < CC; c++) m = fmaxf(m, lg[c]);
        float sum = 0.f;
#pragma unroll
        for (int c = 0; c < CC; c++) sum += expf(lg[c] - m);
        out[b * CC + t] = lg[t] - m - logf(sum);
    }
}

// ---------------- launch ----------------
extern "C" void kernel_launch(void* const* d_in, const int* in_sizes, int n_in,
                              void* d_out, int out_size) {
    const float* x      = (const float*)d_in[0];
    const int*   ei     = (const int*)d_in[1];
    const int*   et     = (const int*)d_in[2];
    const int*   start  = (const int*)d_in[3];
    const float* basis0 = (const float*)d_in[4];
    const float* comp0  = (const float*)d_in[5];
    const float* root0  = (const float*)d_in[6];
    const float* bias0  = (const float*)d_in[7];
    const float* basis  = (const float*)d_in[8];
    const float* comp   = (const float*)d_in[9];
    const float* root   = (const float*)d_in[10];
    const float* bias   = (const float*)d_in[11];
    const float* l1w    = (const float*)d_in[12];
    const float* l1b    = (const float*)d_in[13];
    const float* l2w    = (const float*)d_in[14];
    const float* l2b    = (const float*)d_in[15];
    float* out = (float*)d_out;

    int N = in_sizes[0] / FF;
    int E = in_sizes[2];
    int B = in_sizes[3];

    __half* h0;  cudaGetSymbolAddress((void**)&h0, g_h0);
    __half* h1p; cudaGetSymbolAddress((void**)&h1p, g_h1);

    // ---- CSR build ----
    k_zero_cnt<<<(N * RR + 255) / 256, 256>>>(N * RR);
    k_count<<<(E + 255) / 256, 256>>>(ei, et, E);
    int nblk = (N + 1023) / 1024;
    k_scanA<<<nblk, 1024>>>(N);
    k_scanB<<<1, 256>>>(nblk);
    k_scanC<<<nblk, 1024>>>(N, E);
    k_fill<<<(E + 255) / 256, 256>>>(ei, et, E);

    int nodeBlocks = (N + 7) / 8;
    const int transGrid = 512;

    // ---- layer 0 (in = external fp32 x, F=4) ----
    k_buildW<<<(3 * FF * DD + 255) / 256, 256>>>(root0, basis0, FF);
    k_edge<FF, float><<<nodeBlocks, 256>>>(x, comp0, N);
    k_trans<FF, float><<<transGrid, 256>>>(x, bias0, h0, N);
    k_gather<<<B, 32>>>(h0, start, 0);

    // ---- layers 1..3 (in = out = fp16, D=32) ----
    __half* cur = h0;
    __half* nxt = h1p;
    for (int l = 0; l < 3; l++) {
        k_buildW<<<(3 * DD * DD + 255) / 256, 256>>>(
            root + (size_t)l * DD * DD, basis + (size_t)l * NBB * DD * DD, DD);
        k_edge<DD, __half><<<nodeBlocks, 256>>>(cur, comp + (size_t)l * RR * NBB, N);
        k_trans<DD, __half><<<transGrid, 256>>>(cur, bias + (size_t)l * DD, nxt, N);
        k_gather<<<B, 32>>>(nxt, start, l + 1);
        __half* tmp = cur; cur = nxt; nxt = tmp;
    }

    // ---- readout MLP + log_softmax ----
    k_mlp<<<B, 128>>>(l1w, l1b, l2w, l2b, out);
}

// round 7
// speedup vs baseline: 2.2949x; 1.2220x over previous
#include <cuda_runtime.h>
#include <cuda_fp16.h>
#include <mma.h>
#include <math.h>

using namespace nvcuda;

// Fixed problem constants (IGMC dataset)
#define NMAX 100000
#define EMAX 1600000
#define RR   5
#define DD   32
#define NBB  2
#define FF   4
#define CC   5
#define BMAX 512
#define FULLM 0xffffffffu

// ---------------- scratch (device globals; no allocation) ----------------
// Unified node row: [h(32) | a0(32) | a1(32)] fp16, padded rows for wmma tail.
__device__ __half g_in[(NMAX + 16) * 96];               // 19.2 MB (L2-resident)
__device__ float g_agg0[NMAX * 2 * FF];                 // layer-0 fp32 aggregates (tiny)
__device__ int   g_cntNR[NMAX * RR];
__device__ int   g_rowptr[NMAX + 1];
__device__ int   g_cursor[NMAX];
__device__ int   g_blocksums[128];
__device__ unsigned long long g_recs[EMAX];             // {w_f32 | (src<<3|rel)} dst-sorted
__device__ float  g_W[36 * DD];                         // layer-0 combined W (fp32, K=12)
__device__ __half g_Wh[96 * DD];                        // layers 1-3 combined W (fp16, K=96)
__device__ float g_concat[BMAX * 4 * DD];

// ---------------- CSR build ----------------
__global__ void k_zero_cnt(int n) {
    int i = blockIdx.x * blockDim.x + threadIdx.x;
    if (i < n) g_cntNR[i] = 0;
}

__global__ void k_count(const int* __restrict__ ei, const int* __restrict__ et, int E) {
    int e = blockIdx.x * blockDim.x + threadIdx.x;
    if (e >= E) return;
    int d = ei[E + e];
    int t = et[e];
    atomicAdd(&g_cntNR[d * RR + t], 1);
}

__global__ void k_scanA(int N) {
    __shared__ int s[1024];
    int t = threadIdx.x;
    int i = blockIdx.x * 1024 + t;
    int v = 0;
    if (i < N) {
        int base = i * RR;
#pragma unroll
        for (int r = 0; r < RR; r++) v += g_cntNR[base + r];
    }
    s[t] = v;
    __syncthreads();
    for (int st = 1; st < 1024; st <<= 1) {
        int x = (t >= st) ? s[t - st] : 0;
        __syncthreads();
        s[t] += x;
        __syncthreads();
    }
    if (i < N) g_rowptr[i] = s[t];                      // inclusive within block
    if (t == 1023) g_blocksums[blockIdx.x] = s[1023];
}

// merged scanB+scanC: every block redundantly scans the <=128 block sums
__global__ void k_scanC(int N, int E, int nblk) {
    __shared__ int s[128];
    int t = threadIdx.x;
    if (t < 128) s[t] = (t < nblk) ? g_blocksums[t] : 0;
    __syncthreads();
    for (int st = 1; st < 128; st <<= 1) {
        int x = (t < 128 && t >= st) ? s[t - st] : 0;
        __syncthreads();
        if (t < 128) s[t] += x;
        __syncthreads();
    }
    int myoff = (blockIdx.x == 0) ? 0 : s[blockIdx.x - 1];
    int i = blockIdx.x * 1024 + t;
    if (i < N) {
        int base = i * RR;
        int deg = 0;
#pragma unroll
        for (int r = 0; r < RR; r++) deg += g_cntNR[base + r];
        int excl = g_rowptr[i] - deg + myoff;
        g_rowptr[i] = excl;
        g_cursor[i] = excl;
    }
    if (i == 0) g_rowptr[N] = E;
}

__global__ void k_fill(const int* __restrict__ ei, const int* __restrict__ et, int E) {
    int e = blockIdx.x * blockDim.x + threadIdx.x;
    if (e >= E) return;
    int s = ei[e];
    int d = ei[E + e];
    int t = et[e];
    int p = atomicAdd(&g_cursor[d], 1);
    int c = g_cntNR[d * RR + t];
    float w = 1.0f / (float)c;
    unsigned long long rec =
        (unsigned long long)(unsigned)((s << 3) | t) |
        ((unsigned long long)__float_as_uint(w) << 32);
    g_recs[p] = rec;
}

// ---------------- weight prep ----------------
// Layer 0: fp32 g_W[k][d], k in [0,12): [root(4); basis0(4); basis1(4)]
__global__ void k_buildW0(const float* __restrict__ root, const float* __restrict__ basis) {
    int idx = blockIdx.x * blockDim.x + threadIdx.x;
    if (idx >= 12 * DD) return;
    int k = idx >> 5, d = idx & 31;
    float v;
    if (k < FF) v = root[k * DD + d];
    else {
        int kk = k - FF;
        int b = (kk >= FF) ? 1 : 0;
        int i = kk - b * FF;
        v = basis[(b * FF + i) * DD + d];
    }
    g_W[idx] = v;
}

// Layers 1-3: fp16 g_Wh[k][d], k in [0,96): [root(32); basis0(32); basis1(32)]
__global__ void k_buildWh(const float* __restrict__ root, const float* __restrict__ basis) {
    int idx = blockIdx.x * blockDim.x + threadIdx.x;
    if (idx >= 96 * DD) return;
    int k = idx >> 5, d = idx & 31;
    float v;
    if (k < DD) v = root[k * DD + d];
    else {
        int kk = k - DD;
        int b = (kk >= DD) ? 1 : 0;
        int i = kk - b * DD;
        v = basis[(b * DD + i) * DD + d];
    }
    g_Wh[idx] = __float2half(v);
}

// ---------------- layer 0 (external fp32 x, I=4) ----------------
__global__ void k_edge0(const float* __restrict__ x, const float* __restrict__ comp, int N) {
    int warp = threadIdx.x >> 5, lane = threadIdx.x & 31;
    int n = blockIdx.x * 8 + warp;
    if (n >= N) return;
    float c0reg = (lane < RR) ? comp[lane * NBB + 0] : 0.f;
    float c1reg = (lane < RR) ? comp[lane * NBB + 1] : 0.f;
    float a0 = 0.f, a1 = 0.f;
    int beg = g_rowptr[n];
    int end = g_rowptr[n + 1];
    for (int base = beg; base < end; base += 32) {
        int k = base + lane;
        unsigned long long rec = (k < end) ? g_recs[k] : 0ull;
        unsigned lo = (unsigned)rec;
        float wn = __uint_as_float((unsigned)(rec >> 32));
        int srcL = (int)(lo >> 3);
        int rel = (int)(lo & 7);
        float wc0L = wn * __shfl_sync(FULLM, c0reg, rel);
        float wc1L = wn * __shfl_sync(FULLM, c1reg, rel);
        int cnt = min(32, end - base);
        for (int j = 0; j < cnt; j += 8) {
#pragma unroll
            for (int u = 0; u < 8; u++) {
                int jj = j + u;
                if (jj < cnt) {
                    int s = __shfl_sync(FULLM, srcL, jj);
                    float u0 = __shfl_sync(FULLM, wc0L, jj);
                    float u1 = __shfl_sync(FULLM, wc1L, jj);
                    float v = (lane < FF) ? x[s * FF + lane] : 0.f;
                    a0 += u0 * v;
                    a1 += u1 * v;
                }
            }
        }
    }
    if (lane < FF) {
        g_agg0[n * (2 * FF) + lane] = a0;
        g_agg0[n * (2 * FF) + FF + lane] = a1;
    }
}

__global__ void __launch_bounds__(256) k_trans0(const float* __restrict__ x,
                                                const float* __restrict__ bias, int N) {
    int lane = threadIdx.x & 31;
    float w[12];
#pragma unroll
    for (int k = 0; k < 12; k++) w[k] = g_W[k * DD + lane];
    float bv = bias[lane];
    int warpG = (blockIdx.x * blockDim.x + threadIdx.x) >> 5;
    int nwarps = (gridDim.x * blockDim.x) >> 5;
    for (int n = warpG; n < N; n += nwarps) {
        float iv = 0.f;
        if (lane < FF) iv = x[n * FF + lane];
        else if (lane < 12) iv = g_agg0[n * (2 * FF) + (lane - FF)];
        float acc = bv;
#pragma unroll
        for (int k = 0; k < 12; k++) acc += __shfl_sync(FULLM, iv, k) * w[k];
        g_in[(size_t)n * 96 + lane] = __float2half(tanhf(acc));
    }
}

// ---------------- layers 1-3 ----------------
// Edge aggregation: gather h rows (cols 0:32 of g_in), write fp16 aggregates
// into cols 32:96 of the SAME buffer.
__global__ void k_edgeU(const float* __restrict__ comp, int N) {
    int warp = threadIdx.x >> 5, lane = threadIdx.x & 31;
    int n = blockIdx.x * 8 + warp;
    if (n >= N) return;
    float c0reg = (lane < RR) ? comp[lane * NBB + 0] : 0.f;
    float c1reg = (lane < RR) ? comp[lane * NBB + 1] : 0.f;
    float a0 = 0.f, a1 = 0.f;
    int beg = g_rowptr[n];
    int end = g_rowptr[n + 1];
    for (int base = beg; base < end; base += 32) {
        int k = base + lane;
        unsigned long long rec = (k < end) ? g_recs[k] : 0ull;
        unsigned lo = (unsigned)rec;
        float wn = __uint_as_float((unsigned)(rec >> 32));
        int srcL = (int)(lo >> 3);
        int rel = (int)(lo & 7);
        float wc0L = wn * __shfl_sync(FULLM, c0reg, rel);
        float wc1L = wn * __shfl_sync(FULLM, c1reg, rel);
        int cnt = min(32, end - base);
        for (int j = 0; j < cnt; j += 8) {
#pragma unroll
            for (int u = 0; u < 8; u++) {
                int jj = j + u;
                if (jj < cnt) {
                    int s = __shfl_sync(FULLM, srcL, jj);
                    float u0 = __shfl_sync(FULLM, wc0L, jj);
                    float u1 = __shfl_sync(FULLM, wc1L, jj);
                    float v = __half2float(g_in[(size_t)s * 96 + lane]);
                    a0 += u0 * v;
                    a1 += u1 * v;
                }
            }
        }
    }
    g_in[(size_t)n * 96 + 32 + lane] = __float2half(a0);
    g_in[(size_t)n * 96 + 64 + lane] = __float2half(a1);
}

// Tensor-core transform: rows of g_in [N x 96] @ g_Wh [96 x 32] -> tanh(+bias)
// -> written IN PLACE into cols 0:32 (each tile reads its rows fully before storing).
__global__ void __launch_bounds__(128) k_transW(const float* __restrict__ bias, int N) {
    __shared__ float cbuf[4][16 * 32];
    __shared__ float sbias[32];
    int lane = threadIdx.x & 31;
    int wl = threadIdx.x >> 5;
    if (threadIdx.x < 32) sbias[threadIdx.x] = bias[threadIdx.x];
    __syncthreads();

    int warpG = (blockIdx.x * blockDim.x + threadIdx.x) >> 5;
    int nwarps = (gridDim.x * blockDim.x) >> 5;
    int ntiles = (N + 15) / 16;

    for (int t = warpG; t < ntiles; t += nwarps) {
        int n0 = t * 16;
        wmma::fragment<wmma::accumulator, 16, 16, 16, float> c0, c1;
        wmma::fill_fragment(c0, 0.f);
        wmma::fill_fragment(c1, 0.f);
#pragma unroll
        for (int kk = 0; kk < 6; kk++) {
            wmma::fragment<wmma::matrix_a, 16, 16, 16, __half, wmma::row_major> a;
            wmma::load_matrix_sync(a, g_in + (size_t)n0 * 96 + kk * 16, 96);
            wmma::fragment<wmma::matrix_b, 16, 16, 16, __half, wmma::row_major> b0, b1;
            wmma::load_matrix_sync(b0, g_Wh + kk * 16 * DD, DD);
            wmma::load_matrix_sync(b1, g_Wh + kk * 16 * DD + 16, DD);
            wmma::mma_sync(c0, a, b0, c0);
            wmma::mma_sync(c1, a, b1, c1);
        }
        wmma::store_matrix_sync(&cbuf[wl][0], c0, 32, wmma::mem_row_major);
        wmma::store_matrix_sync(&cbuf[wl][16], c1, 32, wmma::mem_row_major);
        __syncwarp();
#pragma unroll
        for (int i = lane; i < 16 * 32; i += 32) {
            int r = i >> 5, d = i & 31;
            int n = n0 + r;
            if (n < N)
                g_in[(size_t)n * 96 + d] = __float2half(tanhf(cbuf[wl][r * 32 + d] + sbias[d]));
        }
        __syncwarp();
    }
}

__global__ void k_gather(const int* __restrict__ start, int layer) {
    int b = blockIdx.x;
    int lane = threadIdx.x;
    int node = start[b];
    g_concat[b * (4 * DD) + layer * DD + lane] = __half2float(g_in[(size_t)node * 96 + lane]);
}

__global__ void k_mlp(const float* __restrict__ w1, const float* __restrict__ b1,
                      const float* __restrict__ w2, const float* __restrict__ b2,
                      float* __restrict__ out) {
    __shared__ float cs[128];
    __shared__ float h1[128];
    __shared__ float lg[CC];
    int b = blockIdx.x;
    int t = threadIdx.x;
    cs[t] = g_concat[b * 128 + t];
    __syncthreads();
    float s = b1[t];
#pragma unroll 8
    for (int k = 0; k < 128; k++) s += cs[k] * w1[k * 128 + t];
    h1[t] = fmaxf(s, 0.f);
    __syncthreads();
    if (t < CC) {
        float s2 = b2[t];
#pragma unroll 8
        for (int k = 0; k < 128; k++) s2 += h1[k] * w2[k * CC + t];
        lg[t] = s2;
    }
    __syncthreads();
    if (t < CC) {
        float m = lg[0];
#pragma unroll
        for (int c = 1; c < CC; c++) m = fmaxf(m, lg[c]);
        float sum = 0.f;
#pragma unroll
        for (int c = 0; c < CC; c++) sum += expf(lg[c] - m);
        out[b * CC + t] = lg[t] - m - logf(sum);
    }
}

// ---------------- launch ----------------
extern "C" void kernel_launch(void* const* d_in, const int* in_sizes, int n_in,
                              void* d_out, int out_size) {
    const float* x      = (const float*)d_in[0];
    const int*   ei     = (const int*)d_in[1];
    const int*   et     = (const int*)d_in[2];
    const int*   start  = (const int*)d_in[3];
    const float* basis0 = (const float*)d_in[4];
    const float* comp0  = (const float*)d_in[5];
    const float* root0  = (const float*)d_in[6];
    const float* bias0  = (const float*)d_in[7];
    const float* basis  = (const float*)d_in[8];
    const float* comp   = (const float*)d_in[9];
    const float* root   = (const float*)d_in[10];
    const float* bias   = (const float*)d_in[11];
    const float* l1w    = (const float*)d_in[12];
    const float* l1b    = (const float*)d_in[13];
    const float* l2w    = (const float*)d_in[14];
    const float* l2b    = (const float*)d_in[15];
    float* out = (float*)d_out;

    int N = in_sizes[0] / FF;
    int E = in_sizes[2];
    int B = in_sizes[3];

    // ---- CSR build ----
    k_zero_cnt<<<(N * RR + 255) / 256, 256>>>(N * RR);
    k_count<<<(E + 255) / 256, 256>>>(ei, et, E);
    int nblk = (N + 1023) / 1024;
    k_scanA<<<nblk, 1024>>>(N);
    k_scanC<<<nblk, 1024>>>(N, E, nblk);
    k_fill<<<(E + 255) / 256, 256>>>(ei, et, E);

    int nodeBlocks = (N + 7) / 8;

    // ---- layer 0 (in = external fp32 x, F=4) ----
    k_buildW0<<<(12 * DD + 255) / 256, 256>>>(root0, basis0);
    k_edge0<<<nodeBlocks, 256>>>(x, comp0, N);
    k_trans0<<<512, 256>>>(x, bias0, N);
    k_gather<<<B, 32>>>(start, 0);

    // ---- layers 1..3 (unified fp16 rows, wmma transform) ----
    for (int l = 0; l < 3; l++) {
        k_buildWh<<<(96 * DD + 255) / 256, 256>>>(
            root + (size_t)l * DD * DD, basis + (size_t)l * NBB * DD * DD);
        k_edgeU<<<nodeBlocks, 256>>>(comp + (size_t)l * RR * NBB, N);
        k_transW<<<296, 128>>>(bias + (size_t)l * DD, N);
        k_gather<<<B, 32>>>(start, l + 1);
    }

    // ---- readout MLP + log_softmax ----
    k_mlp<<<B, 128>>>(l1w, l1b, l2w, l2b, out);
}

// round 8
// speedup vs baseline: 3.1163x; 1.3579x over previous
#include <cuda_runtime.h>
#include <cuda_fp16.h>
#include <mma.h>
#include <math.h>

using namespace nvcuda;

// Fixed problem constants (IGMC dataset)
#define NMAX 100000
#define EMAX 1600000
#define RR   5
#define DD   32
#define NBB  2
#define FF   4
#define CC   5
#define BMAX 512
#define FULLM 0xffffffffu

// ---------------- scratch (device globals; no allocation) ----------------
// Unified node row: [h(32) | a0(32) | a1(32)] fp16, padded rows for wmma tail.
__device__ __half g_in[(NMAX + 16) * 96];               // 19.2 MB (L2-resident)
__device__ float g_agg0[NMAX * 2 * FF];                 // layer-0 fp32 aggregates
__device__ int   g_cntNR[NMAX * RR];
__device__ int   g_rowptr[NMAX + 1];
__device__ int   g_cursor[NMAX];
__device__ int   g_blocksums[128];
__device__ unsigned long long g_recs[EMAX];             // {w_f32 | (src<<3|rel)} dst-sorted
__device__ float  g_W[12 * DD];                         // layer-0 combined W (fp32, K=12)
__device__ __half g_Wh[3 * 96 * DD];                    // layers 1-3 combined W (fp16, K=96)
__device__ float g_concat[BMAX * 4 * DD];

// ---------------- weight prep (independent of CSR; launched first) ----------------
__global__ void k_buildW0(const float* __restrict__ root, const float* __restrict__ basis) {
    int idx = blockIdx.x * blockDim.x + threadIdx.x;
    if (idx >= 12 * DD) return;
    int k = idx >> 5, d = idx & 31;
    float v;
    if (k < FF) v = root[k * DD + d];
    else {
        int kk = k - FF;
        int b = (kk >= FF) ? 1 : 0;
        int i = kk - b * FF;
        v = basis[(b * FF + i) * DD + d];
    }
    g_W[idx] = v;
}

// All 3 layers at once: g_Wh[l][k][d], k in [0,96): [root(32); basis0(32); basis1(32)]
__global__ void k_buildWhAll(const float* __restrict__ root, const float* __restrict__ basis) {
    int idx = blockIdx.x * blockDim.x + threadIdx.x;
    if (idx >= 3 * 96 * DD) return;
    int l = idx / (96 * DD);
    int rem = idx - l * (96 * DD);
    int k = rem >> 5, d = rem & 31;
    const float* rootl = root + (size_t)l * DD * DD;
    const float* basisl = basis + (size_t)l * NBB * DD * DD;
    float v;
    if (k < DD) v = rootl[k * DD + d];
    else {
        int kk = k - DD;
        int b = (kk >= DD) ? 1 : 0;
        int i = kk - b * DD;
        v = basisl[(b * DD + i) * DD + d];
    }
    g_Wh[idx] = __float2half(v);
}

// ---------------- CSR build ----------------
__global__ void k_zero_cnt(int n) {
    int i = blockIdx.x * blockDim.x + threadIdx.x;
    if (i < n) g_cntNR[i] = 0;
}

__global__ void k_count(const int* __restrict__ ei, const int* __restrict__ et, int E) {
    int e = blockIdx.x * blockDim.x + threadIdx.x;
    if (e >= E) return;
    int d = ei[E + e];
    int t = et[e];
    atomicAdd(&g_cntNR[d * RR + t], 1);
}

__global__ void k_scanA(int N) {
    __shared__ int s[1024];
    int t = threadIdx.x;
    int i = blockIdx.x * 1024 + t;
    int v = 0;
    if (i < N) {
        int base = i * RR;
#pragma unroll
        for (int r = 0; r < RR; r++) v += g_cntNR[base + r];
    }
    s[t] = v;
    __syncthreads();
    for (int st = 1; st < 1024; st <<= 1) {
        int x = (t >= st) ? s[t - st] : 0;
        __syncthreads();
        s[t] += x;
        __syncthreads();
    }
    if (i < N) g_rowptr[i] = s[t];                      // inclusive within block
    if (t == 1023) g_blocksums[blockIdx.x] = s[1023];
}

// merged scanB+scanC: every block redundantly scans the <=128 block sums
__global__ void k_scanC(int N, int E, int nblk) {
    __shared__ int s[128];
    int t = threadIdx.x;
    if (t < 128) s[t] = (t < nblk) ? g_blocksums[t] : 0;
    __syncthreads();
    for (int st = 1; st < 128; st <<= 1) {
        int x = (t < 128 && t >= st) ? s[t - st] : 0;
        __syncthreads();
        if (t < 128) s[t] += x;
        __syncthreads();
    }
    int myoff = (blockIdx.x == 0) ? 0 : s[blockIdx.x - 1];
    int i = blockIdx.x * 1024 + t;
    if (i < N) {
        int base = i * RR;
        int deg = 0;
#pragma unroll
        for (int r = 0; r < RR; r++) deg += g_cntNR[base + r];
        int excl = g_rowptr[i] - deg + myoff;
        g_rowptr[i] = excl;
        g_cursor[i] = excl;
    }
    if (i == 0) g_rowptr[N] = E;
}

__global__ void k_fill(const int* __restrict__ ei, const int* __restrict__ et, int E) {
    int e = blockIdx.x * blockDim.x + threadIdx.x;
    if (e >= E) return;
    int s = ei[e];
    int d = ei[E + e];
    int t = et[e];
    int p = atomicAdd(&g_cursor[d], 1);
    int c = g_cntNR[d * RR + t];
    float w = 1.0f / (float)c;
    unsigned long long rec =
        (unsigned long long)(unsigned)((s << 3) | t) |
        ((unsigned long long)__float_as_uint(w) << 32);
    g_recs[p] = rec;
}

// ---------------- layer 0 (external fp32 x, I=4): 8 edges per warp-iteration ----------------
__global__ void k_edge0(const float* __restrict__ x, const float* __restrict__ comp, int N) {
    int warp = threadIdx.x >> 5, lane = threadIdx.x & 31;
    int n = blockIdx.x * 8 + warp;
    if (n >= N) return;
    float c0reg = (lane < RR) ? comp[lane * NBB + 0] : 0.f;
    float c1reg = (lane < RR) ? comp[lane * NBB + 1] : 0.f;
    int sub = lane >> 2;        // edge slot 0..7
    int dim = lane & 3;
    float a0 = 0.f, a1 = 0.f;
    int beg = g_rowptr[n], end = g_rowptr[n + 1];
    for (int base = beg; base < end; base += 32) {
        int k = base + lane;
        unsigned long long rec = (k < end) ? g_recs[k] : 0ull;
        unsigned lo = (unsigned)rec;
        float wn = __uint_as_float((unsigned)(rec >> 32));
        int srcL = (int)(lo >> 3);
        int rel = (int)(lo & 7);
        float wc0L = wn * __shfl_sync(FULLM, c0reg, rel);
        float wc1L = wn * __shfl_sync(FULLM, c1reg, rel);
        int cnt = min(32, end - base);
#pragma unroll 4
        for (int j = 0; j < cnt; j += 8) {
            int jj = j + sub;
            int s = __shfl_sync(FULLM, srcL, jj);
            float u0 = __shfl_sync(FULLM, wc0L, jj);
            float u1 = __shfl_sync(FULLM, wc1L, jj);
            float v = x[s * FF + dim];
            a0 += u0 * v;
            a1 += u1 * v;
        }
    }
    // reduce across the 8 edge slots (lane bits 2,3,4)
    a0 += __shfl_xor_sync(FULLM, a0, 16); a1 += __shfl_xor_sync(FULLM, a1, 16);
    a0 += __shfl_xor_sync(FULLM, a0, 8);  a1 += __shfl_xor_sync(FULLM, a1, 8);
    a0 += __shfl_xor_sync(FULLM, a0, 4);  a1 += __shfl_xor_sync(FULLM, a1, 4);
    float a1s = __shfl_sync(FULLM, a1, lane & 3);
    float outv = (lane < FF) ? a0 : a1s;
    if (lane < 2 * FF) g_agg0[n * (2 * FF) + lane] = outv;
}

__global__ void __launch_bounds__(256) k_trans0(const float* __restrict__ x,
                                                const float* __restrict__ bias, int N) {
    int lane = threadIdx.x & 31;
    float w[12];
#pragma unroll
    for (int k = 0; k < 12; k++) w[k] = g_W[k * DD + lane];
    float bv = bias[lane];
    int warpG = (blockIdx.x * blockDim.x + threadIdx.x) >> 5;
    int nwarps = (gridDim.x * blockDim.x) >> 5;
    for (int n = warpG; n < N; n += nwarps) {
        float iv = 0.f;
        if (lane < FF) iv = x[n * FF + lane];
        else if (lane < 12) iv = g_agg0[n * (2 * FF) + (lane - FF)];
        float acc = bv;
#pragma unroll
        for (int k = 0; k < 12; k++) acc += __shfl_sync(FULLM, iv, k) * w[k];
        g_in[(size_t)n * 96 + lane] = __float2half(tanhf(acc));
    }
}

// ---------------- layers 1-3 ----------------
// Edge aggregation: 2 edges per warp-iteration. Half-warp per edge, lane covers
// 2 output dims via half2 load. Aggregates -> cols 32:96 of g_in (packed half2).
__global__ void k_edgeU(const float* __restrict__ comp, int N) {
    int warp = threadIdx.x >> 5, lane = threadIdx.x & 31;
    int n = blockIdx.x * 8 + warp;
    if (n >= N) return;
    float c0reg = (lane < RR) ? comp[lane * NBB + 0] : 0.f;
    float c1reg = (lane < RR) ? comp[lane * NBB + 1] : 0.f;
    int sub = lane >> 4;        // edge slot 0 or 1
    int dp = lane & 15;         // dim pair
    float a00 = 0.f, a01 = 0.f, a10 = 0.f, a11 = 0.f;
    int beg = g_rowptr[n], end = g_rowptr[n + 1];
    for (int base = beg; base < end; base += 32) {
        int k = base + lane;
        unsigned long long rec = (k < end) ? g_recs[k] : 0ull;
        unsigned lo = (unsigned)rec;
        float wn = __uint_as_float((unsigned)(rec >> 32));
        int srcL = (int)(lo >> 3);
        int rel = (int)(lo & 7);
        float wc0L = wn * __shfl_sync(FULLM, c0reg, rel);
        float wc1L = wn * __shfl_sync(FULLM, c1reg, rel);
        int cnt = min(32, end - base);
        for (int j = 0; j < cnt; j += 8) {
#pragma unroll
            for (int u = 0; u < 8; u += 2) {
                int jj = j + u + sub;
                int s = __shfl_sync(FULLM, srcL, jj);
                float u0 = __shfl_sync(FULLM, wc0L, jj);
                float u1 = __shfl_sync(FULLM, wc1L, jj);
                __half2 v2 = *reinterpret_cast<const __half2*>(&g_in[(size_t)s * 96 + 2 * dp]);
                float2 vf = __half22float2(v2);
                a00 += u0 * vf.x; a01 += u0 * vf.y;
                a10 += u1 * vf.x; a11 += u1 * vf.y;
            }
        }
    }
    // merge the two edge subsets
    a00 += __shfl_xor_sync(FULLM, a00, 16);
    a01 += __shfl_xor_sync(FULLM, a01, 16);
    a10 += __shfl_xor_sync(FULLM, a10, 16);
    a11 += __shfl_xor_sync(FULLM, a11, 16);
    __half2* rowout = reinterpret_cast<__half2*>(&g_in[(size_t)n * 96 + 32]);
    if (sub == 0) rowout[dp] = __floats2half2_rn(a00, a01);
    else          rowout[16 + dp] = __floats2half2_rn(a10, a11);
}

// Tensor-core transform: g_in [N x 96] @ g_Wh[l] [96 x 32] -> tanh(+bias), in place cols 0:32
__global__ void __launch_bounds__(128) k_transW(const float* __restrict__ bias, int layer, int N) {
    __shared__ float cbuf[4][16 * 32];
    __shared__ float sbias[32];
    int lane = threadIdx.x & 31;
    int wl = threadIdx.x >> 5;
    if (threadIdx.x < 32) sbias[threadIdx.x] = bias[threadIdx.x];
    __syncthreads();
    const __half* Wl = g_Wh + (size_t)layer * 96 * DD;

    int warpG = (blockIdx.x * blockDim.x + threadIdx.x) >> 5;
    int nwarps = (gridDim.x * blockDim.x) >> 5;
    int ntiles = (N + 15) / 16;

    for (int t = warpG; t < ntiles; t += nwarps) {
        int n0 = t * 16;
        wmma::fragment<wmma::accumulator, 16, 16, 16, float> c0, c1;
        wmma::fill_fragment(c0, 0.f);
        wmma::fill_fragment(c1, 0.f);
#pragma unroll
        for (int kk = 0; kk < 6; kk++) {
            wmma::fragment<wmma::matrix_a, 16, 16, 16, __half, wmma::row_major> a;
            wmma::load_matrix_sync(a, g_in + (size_t)n0 * 96 + kk * 16, 96);
            wmma::fragment<wmma::matrix_b, 16, 16, 16, __half, wmma::row_major> b0, b1;
            wmma::load_matrix_sync(b0, Wl + kk * 16 * DD, DD);
            wmma::load_matrix_sync(b1, Wl + kk * 16 * DD + 16, DD);
            wmma::mma_sync(c0, a, b0, c0);
            wmma::mma_sync(c1, a, b1, c1);
        }
        wmma::store_matrix_sync(&cbuf[wl][0], c0, 32, wmma::mem_row_major);
        wmma::store_matrix_sync(&cbuf[wl][16], c1, 32, wmma::mem_row_major);
        __syncwarp();
#pragma unroll
        for (int i = lane; i < 16 * 32; i += 32) {
            int r = i >> 5, d = i & 31;
            int n = n0 + r;
            if (n < N)
                g_in[(size_t)n * 96 + d] = __float2half(tanhf(cbuf[wl][r * 32 + d] + sbias[d]));
        }
        __syncwarp();
    }
}

__global__ void k_gather(const int* __restrict__ start, int layer) {
    int b = blockIdx.x;
    int lane = threadIdx.x;
    int node = start[b];
    g_concat[b * (4 * DD) + layer * DD + lane] = __half2float(g_in[(size_t)node * 96 + lane]);
}

__global__ void k_mlp(const float* __restrict__ w1, const float* __restrict__ b1,
                      const float* __restrict__ w2, const float* __restrict__ b2,
                      float* __restrict__ out) {
    __shared__ float cs[128];
    __shared__ float h1[128];
    __shared__ float lg[CC];
    int b = blockIdx.x;
    int t = threadIdx.x;
    cs[t] = g_concat[b * 128 + t];
    __syncthreads();
    float s = b1[t];
#pragma unroll 8
    for (int k = 0; k < 128; k++) s += cs[k] * w1[k * 128 + t];
    h1[t] = fmaxf(s, 0.f);
    __syncthreads();
    if (t < CC) {
        float s2 = b2[t];
#pragma unroll 8
        for (int k = 0; k < 128; k++) s2 += h1[k] * w2[k * CC + t];
        lg[t] = s2;
    }
    __syncthreads();
    if (t < CC) {
        float m = lg[0];
#pragma unroll
        for (int c = 1; c < CC; c++) m = fmaxf(m, lg[c]);
        float sum = 0.f;
#pragma unroll
        for (int c = 0; c < CC; c++) sum += expf(lg[c] - m);
        out[b * CC + t] = lg[t] - m - logf(sum);
    }
}

// ---------------- launch ----------------
extern "C" void kernel_launch(void* const* d_in, const int* in_sizes, int n_in,
                              void* d_out, int out_size) {
    const float* x      = (const float*)d_in[0];
    const int*   ei     = (const int*)d_in[1];
    const int*   et     = (const int*)d_in[2];
    const int*   start  = (const int*)d_in[3];
    const float* basis0 = (const float*)d_in[4];
    const float* comp0  = (const float*)d_in[5];
    const float* root0  = (const float*)d_in[6];
    const float* bias0  = (const float*)d_in[7];
    const float* basis  = (const float*)d_in[8];
    const float* comp   = (const float*)d_in[9];
    const float* root   = (const float*)d_in[10];
    const float* bias   = (const float*)d_in[11];
    const float* l1w    = (const float*)d_in[12];
    const float* l1b    = (const float*)d_in[13];
    const float* l2w    = (const float*)d_in[14];
    const float* l2b    = (const float*)d_in[15];
    float* out = (float*)d_out;

    int N = in_sizes[0] / FF;
    int E = in_sizes[2];
    int B = in_sizes[3];

    // ---- weight prep (no CSR dependency) ----
    k_buildW0<<<(12 * DD + 255) / 256, 256>>>(root0, basis0);
    k_buildWhAll<<<(3 * 96 * DD + 255) / 256, 256>>>(root, basis);

    // ---- CSR build ----
    k_zero_cnt<<<(N * RR + 255) / 256, 256>>>(N * RR);
    k_count<<<(E + 255) / 256, 256>>>(ei, et, E);
    int nblk = (N + 1023) / 1024;
    k_scanA<<<nblk, 1024>>>(N);
    k_scanC<<<nblk, 1024>>>(N, E, nblk);
    k_fill<<<(E + 255) / 256, 256>>>(ei, et, E);

    int nodeBlocks = (N + 7) / 8;

    // ---- layer 0 (in = external fp32 x, F=4) ----
    k_edge0<<<nodeBlocks, 256>>>(x, comp0, N);
    k_trans0<<<512, 256>>>(x, bias0, N);
    k_gather<<<B, 32>>>(start, 0);

    // ---- layers 1..3 (unified fp16 rows, wmma transform) ----
    for (int l = 0; l < 3; l++) {
        k_edgeU<<<nodeBlocks, 256>>>(comp + (size_t)l * RR * NBB, N);
        k_transW<<<296, 128>>>(bias + (size_t)l * DD, l, N);
        k_gather<<<B, 32>>>(start, l + 1);
    }

    // ---- readout MLP + log_softmax ----
    k_mlp<<<B, 128>>>(l1w, l1b, l2w, l2b, out);
}

// round 11
// speedup vs baseline: 3.2560x; 1.0448x over previous
#include <cuda_runtime.h>
#include <cuda_fp16.h>
#include <mma.h>
#include <math.h>

using namespace nvcuda;

// Fixed problem constants (IGMC dataset)
#define NMAX 100000
#define EMAX 1600000
#define RR   5
#define DD   32
#define NBB  2
#define FF   4
#define CC   5
#define BMAX 512
#define FULLM 0xffffffffu

// ---------------- scratch (device globals; no allocation) ----------------
// Unified node row: [h(32) | a0(32) | a1(32)] fp16, padded rows for wmma tail.
__device__ __align__(16) __half g_in[(NMAX + 16) * 96];     // 19.2 MB (L2-resident)
__device__ __align__(16) __half g_hist[4 * NMAX * DD];      // per-layer h history (25.6 MB)
__device__ float g_agg0[NMAX * 2 * FF];                     // layer-0 fp32 aggregates
__device__ int   g_cntNR[NMAX * RR];                        // zeroed at end of each call
__device__ int   g_rowptr[NMAX + 1];
__device__ int   g_cursor[NMAX];
__device__ int   g_blocksums[128];
__device__ unsigned g_recs[EMAX];                           // {cnt:12|src:17|rel:3} dst-sorted
__device__ float  g_W[12 * DD];                             // layer-0 combined W (fp32, K=12)
__device__ __half g_Wh[3 * 96 * DD];                        // layers 1-3 combined W (fp16)

// ---------------- weight prep (independent of CSR; launched first) ----------------
__global__ void k_buildW0(const float* __restrict__ root, const float* __restrict__ basis) {
    int idx = blockIdx.x * blockDim.x + threadIdx.x;
    if (idx >= 12 * DD) return;
    int k = idx >> 5, d = idx & 31;
    float v;
    if (k < FF) v = root[k * DD + d];
    else {
        int kk = k - FF;
        int b = (kk >= FF) ? 1 : 0;
        int i = kk - b * FF;
        v = basis[(b * FF + i) * DD + d];
    }
    g_W[idx] = v;
}

__global__ void k_buildWhAll(const float* __restrict__ root, const float* __restrict__ basis) {
    int idx = blockIdx.x * blockDim.x + threadIdx.x;
    if (idx >= 3 * 96 * DD) return;
    int l = idx / (96 * DD);
    int rem = idx - l * (96 * DD);
    int k = rem >> 5, d = rem & 31;
    const float* rootl = root + (size_t)l * DD * DD;
    const float* basisl = basis + (size_t)l * NBB * DD * DD;
    float v;
    if (k < DD) v = rootl[k * DD + d];
    else {
        int kk = k - DD;
        int b = (kk >= DD) ? 1 : 0;
        int i = kk - b * DD;
        v = basisl[(b * DD + i) * DD + d];
    }
    g_Wh[idx] = __float2half(v);
}

// ---------------- CSR build ----------------
__global__ void k_count(const int* __restrict__ ei, const int* __restrict__ et, int E) {
    int e = blockIdx.x * blockDim.x + threadIdx.x;
    if (e >= E) return;
    int d = ei[E + e];
    int t = et[e];
    atomicAdd(&g_cntNR[d * RR + t], 1);
}

__global__ void k_scanA(int N) {
    __shared__ int s[1024];
    int t = threadIdx.x;
    int i = blockIdx.x * 1024 + t;
    int v = 0;
    if (i < N) {
        int base = i * RR;
#pragma unroll
        for (int r = 0; r < RR; r++) v += g_cntNR[base + r];
    }
    s[t] = v;
    __syncthreads();
    for (int st = 1; st < 1024; st <<= 1) {
        int x = (t >= st) ? s[t - st] : 0;
        __syncthreads();
        s[t] += x;
        __syncthreads();
    }
    if (i < N) g_rowptr[i] = s[t];
    if (t == 1023) g_blocksums[blockIdx.x] = s[1023];
}

__global__ void k_scanC(int N, int E, int nblk) {
    __shared__ int s[128];
    int t = threadIdx.x;
    if (t < 128) s[t] = (t < nblk) ? g_blocksums[t] : 0;
    __syncthreads();
    for (int st = 1; st < 128; st <<= 1) {
        int x = (t < 128 && t >= st) ? s[t - st] : 0;
        __syncthreads();
        if (t < 128) s[t] += x;
        __syncthreads();
    }
    int myoff = (blockIdx.x == 0) ? 0 : s[blockIdx.x - 1];
    int i = blockIdx.x * 1024 + t;
    if (i < N) {
        int base = i * RR;
        int deg = 0;
#pragma unroll
        for (int r = 0; r < RR; r++) deg += g_cntNR[base + r];
        int excl = g_rowptr[i] - deg + myoff;
        g_rowptr[i] = excl;
        g_cursor[i] = excl;
    }
    if (i == 0) g_rowptr[N] = E;
}

__global__ void k_fill(const int* __restrict__ ei, const int* __restrict__ et, int E) {
    int e = blockIdx.x * blockDim.x + threadIdx.x;
    if (e >= E) return;
    int s = ei[e];
    int d = ei[E + e];
    int t = et[e];
    int p = atomicAdd(&g_cursor[d], 1);
    unsigned c = (unsigned)g_cntNR[d * RR + t];     // 1..4095
    g_recs[p] = (c << 20) | ((unsigned)s << 3) | (unsigned)t;
}

// per-lane record decode at batch setup
__device__ __forceinline__ void decode_rec(unsigned rec, const float c0reg, const float c1reg,
                                           int& srcL, float& wc0L, float& wc1L) {
    int rel = (int)(rec & 7u);
    srcL = (int)((rec >> 3) & 0x1FFFFu);
    float w = rec ? __fdividef(1.0f, (float)(rec >> 20)) : 0.f;
    wc0L = w * __shfl_sync(FULLM, c0reg, rel);
    wc1L = w * __shfl_sync(FULLM, c1reg, rel);
}

// ---------------- layer 0 (external fp32 x, I=4): 8 edges per warp-iteration ----------------
// Also re-zeroes g_cntNR for the next call (grid-stride; cntNR has no later reader).
__global__ void k_edge0(const float* __restrict__ x, const float* __restrict__ comp, int N) {
    int gidx = blockIdx.x * blockDim.x + threadIdx.x;
    if (gidx < NMAX * RR) g_cntNR[gidx] = 0;

    int warp = threadIdx.x >> 5, lane = threadIdx.x & 31;
    int n = blockIdx.x * 8 + warp;
    if (n >= N) return;
    float c0reg = (lane < RR) ? comp[lane * NBB + 0] : 0.f;
    float c1reg = (lane < RR) ? comp[lane * NBB + 1] : 0.f;
    int sub = lane >> 2;        // edge slot 0..7
    int dim = lane & 3;
    float a0 = 0.f, a1 = 0.f;
    int beg = g_rowptr[n], end = g_rowptr[n + 1];
    for (int base = beg; base < end; base += 32) {
        int k = base + lane;
        unsigned rec = (k < end) ? g_recs[k] : 0u;
        int srcL; float wc0L, wc1L;
        decode_rec(rec, c0reg, c1reg, srcL, wc0L, wc1L);
        int cnt = min(32, end - base);
#pragma unroll 4
        for (int j = 0; j < cnt; j += 8) {
            int jj = j + sub;
            int s = __shfl_sync(FULLM, srcL, jj);
            float u0 = __shfl_sync(FULLM, wc0L, jj);
            float u1 = __shfl_sync(FULLM, wc1L, jj);
            float v = x[s * FF + dim];
            a0 += u0 * v;
            a1 += u1 * v;
        }
    }
    a0 += __shfl_xor_sync(FULLM, a0, 16); a1 += __shfl_xor_sync(FULLM, a1, 16);
    a0 += __shfl_xor_sync(FULLM, a0, 8);  a1 += __shfl_xor_sync(FULLM, a1, 8);
    a0 += __shfl_xor_sync(FULLM, a0, 4);  a1 += __shfl_xor_sync(FULLM, a1, 4);
    float a1s = __shfl_sync(FULLM, a1, lane & 3);
    float outv = (lane < FF) ? a0 : a1s;
    if (lane < 2 * FF) g_agg0[n * (2 * FF) + lane] = outv;
}

__global__ void __launch_bounds__(256) k_trans0(const float* __restrict__ x,
                                                const float* __restrict__ bias, int N) {
    int lane = threadIdx.x & 31;
    float w[12];
#pragma unroll
    for (int k = 0; k < 12; k++) w[k] = g_W[k * DD + lane];
    float bv = bias[lane];
    int warpG = (blockIdx.x * blockDim.x + threadIdx.x) >> 5;
    int nwarps = (gridDim.x * blockDim.x) >> 5;
    for (int n = warpG; n < N; n += nwarps) {
        float iv = 0.f;
        if (lane < FF) iv = x[n * FF + lane];
        else if (lane < 12) iv = g_agg0[n * (2 * FF) + (lane - FF)];
        float acc = bv;
#pragma unroll
        for (int k = 0; k < 12; k++) acc += __shfl_sync(FULLM, iv, k) * w[k];
        __half hv = __float2half(tanhf(acc));
        g_in[(size_t)n * 96 + lane] = hv;
        g_hist[(size_t)n * DD + lane] = hv;
    }
}

// ---------------- layers 1-3 ----------------
// Edge aggregation: 4 edges per warp-iteration. 8 lanes per edge; each lane
// covers 4 output dims via one 8B load. Aggregates -> cols 32:96 of g_in.
__global__ void k_edgeU(const float* __restrict__ comp, int N) {
    int warp = threadIdx.x >> 5, lane = threadIdx.x & 31;
    int n = blockIdx.x * 8 + warp;
    if (n >= N) return;
    float c0reg = (lane < RR) ? comp[lane * NBB + 0] : 0.f;
    float c1reg = (lane < RR) ? comp[lane * NBB + 1] : 0.f;
    int sub = lane >> 3;        // edge slot 0..3
    int dq = lane & 7;          // dim quad: dims [4dq, 4dq+4)
    float a00 = 0.f, a01 = 0.f, a02 = 0.f, a03 = 0.f;
    float a10 = 0.f, a11 = 0.f, a12 = 0.f, a13 = 0.f;
    int beg = g_rowptr[n], end = g_rowptr[n + 1];
    for (int base = beg; base < end; base += 32) {
        int k = base + lane;
        unsigned rec = (k < end) ? g_recs[k] : 0u;
        int srcL; float wc0L, wc1L;
        decode_rec(rec, c0reg, c1reg, srcL, wc0L, wc1L);
        int cnt = min(32, end - base);
#pragma unroll 2
        for (int j = 0; j < cnt; j += 4) {
            int jj = j + sub;
            int s = __shfl_sync(FULLM, srcL, jj);
            float u0 = __shfl_sync(FULLM, wc0L, jj);
            float u1 = __shfl_sync(FULLM, wc1L, jj);
            uint2 raw = *reinterpret_cast<const uint2*>(&g_in[(size_t)s * 96 + 4 * dq]);
            float2 fa = __half22float2(*reinterpret_cast<__half2*>(&raw.x));
            float2 fb = __half22float2(*reinterpret_cast<__half2*>(&raw.y));
            a00 += u0 * fa.x; a01 += u0 * fa.y; a02 += u0 * fb.x; a03 += u0 * fb.y;
            a10 += u1 * fa.x; a11 += u1 * fa.y; a12 += u1 * fb.x; a13 += u1 * fb.y;
        }
    }
    // merge the 4 edge subsets (lane bits 3,4)
    a00 += __shfl_xor_sync(FULLM, a00, 8);  a01 += __shfl_xor_sync(FULLM, a01, 8);
    a02 += __shfl_xor_sync(FULLM, a02, 8);  a03 += __shfl_xor_sync(FULLM, a03, 8);
    a10 += __shfl_xor_sync(FULLM, a10, 8);  a11 += __shfl_xor_sync(FULLM, a11, 8);
    a12 += __shfl_xor_sync(FULLM, a12, 8);  a13 += __shfl_xor_sync(FULLM, a13, 8);
    a00 += __shfl_xor_sync(FULLM, a00, 16); a01 += __shfl_xor_sync(FULLM, a01, 16);
    a02 += __shfl_xor_sync(FULLM, a02, 16); a03 += __shfl_xor_sync(FULLM, a03, 16);
    a10 += __shfl_xor_sync(FULLM, a10, 16); a11 += __shfl_xor_sync(FULLM, a11, 16);
    a12 += __shfl_xor_sync(FULLM, a12, 16); a13 += __shfl_xor_sync(FULLM, a13, 16);
    if (sub == 0) {
        uint2 pk;
        *reinterpret_cast<__half2*>(&pk.x) = __floats2half2_rn(a00, a01);
        *reinterpret_cast<__half2*>(&pk.y) = __floats2half2_rn(a02, a03);
        *reinterpret_cast<uint2*>(&g_in[(size_t)n * 96 + 32 + 4 * dq]) = pk;
    } else if (sub == 1) {
        uint2 pk;
        *reinterpret_cast<__half2*>(&pk.x) = __floats2half2_rn(a10, a11);
        *reinterpret_cast<__half2*>(&pk.y) = __floats2half2_rn(a12, a13);
        *reinterpret_cast<uint2*>(&g_in[(size_t)n * 96 + 64 + 4 * dq]) = pk;
    }
}

// Tensor-core transform: g_in [N x 96] @ g_Wh[l] [96 x 32] -> tanh(+bias),
// written in place (cols 0:32) and into the layer history buffer.
__global__ void __launch_bounds__(128) k_transW(const float* __restrict__ bias, int layer, int N) {
    __shared__ float cbuf[4][16 * 32];
    __shared__ float sbias[32];
    int lane = threadIdx.x & 31;
    int wl = threadIdx.x >> 5;
    if (threadIdx.x < 32) sbias[threadIdx.x] = bias[threadIdx.x];
    __syncthreads();
    const __half* Wl = g_Wh + (size_t)layer * 96 * DD;
    __half* hist = g_hist + (size_t)(layer + 1) * NMAX * DD;

    int warpG = (blockIdx.x * blockDim.x + threadIdx.x) >> 5;
    int nwarps = (gridDim.x * blockDim.x) >> 5;
    int ntiles = (N + 15) / 16;

    for (int t = warpG; t < ntiles; t += nwarps) {
        int n0 = t * 16;
        wmma::fragment<wmma::accumulator, 16, 16, 16, float> c0, c1;
        wmma::fill_fragment(c0, 0.f);
        wmma::fill_fragment(c1, 0.f);
#pragma unroll
        for (int kk = 0; kk < 6; kk++) {
            wmma::fragment<wmma::matrix_a, 16, 16, 16, __half, wmma::row_major> a;
            wmma::load_matrix_sync(a, g_in + (size_t)n0 * 96 + kk * 16, 96);
            wmma::fragment<wmma::matrix_b, 16, 16, 16, __half, wmma::row_major> b0, b1;
            wmma::load_matrix_sync(b0, Wl + kk * 16 * DD, DD);
            wmma::load_matrix_sync(b1, Wl + kk * 16 * DD + 16, DD);
            wmma::mma_sync(c0, a, b0, c0);
            wmma::mma_sync(c1, a, b1, c1);
        }
        wmma::store_matrix_sync(&cbuf[wl][0], c0, 32, wmma::mem_row_major);
        wmma::store_matrix_sync(&cbuf[wl][16], c1, 32, wmma::mem_row_major);
        __syncwarp();
#pragma unroll
        for (int i = lane; i < 16 * 16; i += 32) {
            int r = i >> 4, dp = i & 15;
            int n = n0 + r;
            if (n < N) {
                float v0 = tanhf(cbuf[wl][r * 32 + 2 * dp] + sbias[2 * dp]);
                float v1 = tanhf(cbuf[wl][r * 32 + 2 * dp + 1] + sbias[2 * dp + 1]);
                __half2 hv = __floats2half2_rn(v0, v1);
                *reinterpret_cast<__half2*>(&g_in[(size_t)n * 96 + 2 * dp]) = hv;
                *reinterpret_cast<__half2*>(&hist[(size_t)n * DD + 2 * dp]) = hv;
            }
        }
        __syncwarp();
    }
}

// MLP head: reads the 4-layer concat directly from g_hist
__global__ void k_mlp(const int* __restrict__ start,
                      const float* __restrict__ w1, const float* __restrict__ b1,
                      const float* __restrict__ w2, const float* __restrict__ b2,
                      float* __restrict__ out) {
    __shared__ float cs[128];
    __shared__ float h1[128];
    __shared__ float lg[CC];
    int b = blockIdx.x;
    int t = threadIdx.x;
    int node = start[b];
    int layer = t >> 5, d = t & 31;
    cs[t] = __half2float(g_hist[(size_t)layer * NMAX * DD + (size_t)node * DD + d]);
    __syncthreads();
    float s = b1[t];
#pragma unroll 8
    for (int k = 0; k < 128; k++) s += cs[k] * w1[k * 128 + t];
    h1[t] = fmaxf(s, 0.f);
    __syncthreads();
    if (t < CC) {
        float s2 = b2[t];
#pragma unroll 8
        for (int k = 0; k < 128; k++) s2 += h1[k] * w2[k * CC + t];
        lg[t] = s2;
    }
    __syncthreads();
    if (t < CC) {
        float m = lg[0];
#pragma unroll
        for (int c = 1; c < CC; c++) m = fmaxf(m, lg[c]);
        float sum = 0.f;
#pragma unroll
        for (int c = 0; c < CC; c++) sum += expf(lg[c] - m);
        out[b * CC + t] = lg[t] - m - logf(sum);
    }
}

// ---------------- launch ----------------
extern "C" void kernel_launch(void* const* d_in, const int* in_sizes, int n_in,
                              void* d_out, int out_size) {
    const float* x      = (const float*)d_in[0];
    const int*   ei     = (const int*)d_in[1];
    const int*   et     = (const int*)d_in[2];
    const int*   start  = (const int*)d_in[3];
    const float* basis0 = (const float*)d_in[4];
    const float* comp0  = (const float*)d_in[5];
    const float* root0  = (const float*)d_in[6];
    const float* bias0  = (const float*)d_in[7];
    const float* basis  = (const float*)d_in[8];
    const float* comp   = (const float*)d_in[9];
    const float* root   = (const float*)d_in[10];
    const float* bias   = (const float*)d_in[11];
    const float* l1w    = (const float*)d_in[12];
    const float* l1b    = (const float*)d_in[13];
    const float* l2w    = (const float*)d_in[14];
    const float* l2b    = (const float*)d_in[15];
    float* out = (float*)d_out;

    int N = in_sizes[0] / FF;
    int E = in_sizes[2];
    int B = in_sizes[3];

    // ---- weight prep (no CSR dependency) ----
    k_buildW0<<<(12 * DD + 255) / 256, 256>>>(root0, basis0);
    k_buildWhAll<<<(3 * 96 * DD + 255) / 256, 256>>>(root, basis);

    // ---- CSR build (g_cntNR arrives zeroed: initial state / re-zeroed by k_edge0) ----
    k_count<<<(E + 255) / 256, 256>>>(ei, et, E);
    int nblk = (N + 1023) / 1024;
    k_scanA<<<nblk, 1024>>>(N);
    k_scanC<<<nblk, 1024>>>(N, E, nblk);
    k_fill<<<(E + 255) / 256, 256>>>(ei, et, E);

    int nodeBlocks = (N + 7) / 8;

    // ---- layer 0 (in = external fp32 x, F=4) ----
    k_edge0<<<nodeBlocks, 256>>>(x, comp0, N);
    k_trans0<<<512, 256>>>(x, bias0, N);

    // ---- layers 1..3 (unified fp16 rows, wmma transform) ----
    for (int l = 0; l < 3; l++) {
        k_edgeU<<<nodeBlocks, 256>>>(comp + (size_t)l * RR * NBB, N);
        k_transW<<<296, 128>>>(bias + (size_t)l * DD, l, N);
    }

    // ---- readout MLP + log_softmax ----
    k_mlp<<<B, 128>>>(start, l1w, l1b, l2w, l2b, out);
}